// round 12
// baseline (speedup 1.0000x reference)
#include <cuda_runtime.h>

#define EMBED     128
#define MAXN      200
#define NTHREADS  256
#define LN_EPS    1e-5f

// Interleaved pre-transposed weights: g_Wp[e*128+d] = (W_tail[d][e], W_head[d][e])
__device__ float2 g_Wp[EMBED * EMBED];

__global__ void transpose_w(const float* __restrict__ Wt, const float* __restrict__ Wh) {
    int i = blockIdx.x * blockDim.x + threadIdx.x;
    if (i < EMBED * EMBED) {
        int d = i >> 7;
        int e = i & 127;
        g_Wp[e * EMBED + d] = make_float2(Wt[i], Wh[i]);
    }
}

// One CTA = one batch element, BOTH sides. Score+exp+aggregate fused, 4 rows/iter.
__global__ __launch_bounds__(NTHREADS, 5)
void encoder_kernel(const int*   __restrict__ entity,
                    const int*   __restrict__ conn_left,
                    const int*   __restrict__ conn_right,
                    const float* __restrict__ emb,
                    const float* __restrict__ W_bil,
                    const float* __restrict__ gamma,
                    const float* __restrict__ beta,
                    float*       __restrict__ out,
                    int batch, int pad_idx)
{
    const int b    = blockIdx.x;
    const int tid  = threadIdx.x;
    const int lane = tid & 31;
    const int wid  = tid >> 5;

    __shared__ float s_weak[EMBED];
    __shared__ float s_head[2][EMBED];
    __shared__ float s_qp[2 * EMBED];
    __shared__ __align__(16) unsigned s_roff[2][MAXN];   // rel row byte-offsets
    __shared__ __align__(16) unsigned s_toff[2][MAXN];   // tail row byte-offsets
    __shared__ float s_aggp[8][EMBED];
    __shared__ float s_agg[2][EMBED];
    __shared__ float s_part[2][2][EMBED];
    __shared__ float s_red[8];
    __shared__ float s_red2[8];

    // ---- Stage 0: heads, weak_rel, neighbor offsets for both sides ----
    if (tid < EMBED) {
        int e0 = entity[2 * b];
        int e1 = entity[2 * b + 1];
        float hl = emb[(size_t)e0 * EMBED + tid];
        float hr = emb[(size_t)e1 * EMBED + tid];
        s_weak[tid]    = hr - hl;
        s_head[0][tid] = hl;
        s_head[1][tid] = hr;
    }
    for (int i = tid; i < 2 * MAXN; i += NTHREADS) {
        int s = (i < MAXN) ? 0 : 1;
        int m = (i < MAXN) ? i : i - MAXN;
        const int* conn = (s == 0 ? conn_left : conn_right) + (long)b * MAXN * 2;
        int2 c = reinterpret_cast<const int2*>(conn)[m];
        s_roff[s][m] = (unsigned)c.x << 9;     // row * 512 bytes
        s_toff[s][m] = (unsigned)c.y << 9;
    }
    __syncthreads();

    // ---- Stage 1: q = weak_rel @ W_bil (shared by both sides), split-K ----
    {
        int half = tid >> 7;
        int e    = tid & 127;
        int d0   = half * 64;
        float acc = 0.f;
        #pragma unroll 8
        for (int d = d0; d < d0 + 64; d++)
            acc = fmaf(s_weak[d], W_bil[d * EMBED + e], acc);
        s_qp[half * EMBED + e] = acc;
    }
    __syncthreads();

    // ---- Stage 2 (FUSED): score -> exp -> aggregate, 4 rows per iteration ----
    {
        float4 q0 = reinterpret_cast<const float4*>(s_qp)[lane];
        float4 q1 = reinterpret_cast<const float4*>(s_qp + EMBED)[lane];
        float4 qv = make_float4(q0.x + q1.x, q0.y + q1.y, q0.z + q1.z, q0.w + q1.w);

        const char* embB = reinterpret_cast<const char*>(emb) + (unsigned)(lane << 4);
        const unsigned pad_off = (unsigned)pad_idx << 9;

        const int s    = wid >> 2;
        const int w4   = wid & 3;
        const bool hi16 = (lane & 16) != 0;
        const bool hi8  = (lane & 8)  != 0;

        float  lsum = 0.f;
        float4 a01 = make_float4(0.f, 0.f, 0.f, 0.f);
        float4 a23 = make_float4(0.f, 0.f, 0.f, 0.f);

        // 4-row fused body; m is a multiple of 4 (int4-aligned offset loads)
        auto body4 = [&](int m) {
            int4 ro = *reinterpret_cast<const int4*>(&s_roff[s][m]);
            int4 to = *reinterpret_cast<const int4*>(&s_toff[s][m]);
            // this lane-group's row offset for the pad check (frees ro early):
            // groups after reduce: [0-7]=row0, [8-15]=row2, [16-23]=row1, [24-31]=row3
            unsigned gA = hi8  ? (unsigned)ro.z : (unsigned)ro.x;
            unsigned gB = hi8  ? (unsigned)ro.w : (unsigned)ro.y;
            unsigned my_off = hi16 ? gB : gA;

            float4 v0 = *reinterpret_cast<const float4*>(embB + (unsigned)ro.x);
            float4 v1 = *reinterpret_cast<const float4*>(embB + (unsigned)ro.y);
            float4 v2 = *reinterpret_cast<const float4*>(embB + (unsigned)ro.z);
            float4 v3 = *reinterpret_cast<const float4*>(embB + (unsigned)ro.w);
            float4 u0 = *reinterpret_cast<const float4*>(embB + (unsigned)to.x);
            float4 u1 = *reinterpret_cast<const float4*>(embB + (unsigned)to.y);
            float4 u2 = *reinterpret_cast<const float4*>(embB + (unsigned)to.z);
            float4 u3 = *reinterpret_cast<const float4*>(embB + (unsigned)to.w);

            float p0 = v0.x*qv.x + v0.y*qv.y + v0.z*qv.z + v0.w*qv.w;
            float p1 = v1.x*qv.x + v1.y*qv.y + v1.z*qv.z + v1.w*qv.w;
            float p2 = v2.x*qv.x + v2.y*qv.y + v2.z*qv.z + v2.w*qv.w;
            float p3 = v3.x*qv.x + v3.y*qv.y + v3.z*qv.z + v3.w*qv.w;

            // 4-row reduce in 5 shfls
            float x01 = hi16 ? p1 : p0;
            float y01 = hi16 ? p0 : p1;
            x01 += __shfl_xor_sync(0xffffffffu, y01, 16);
            float x23 = hi16 ? p3 : p2;
            float y23 = hi16 ? p2 : p3;
            x23 += __shfl_xor_sync(0xffffffffu, y23, 16);
            float x = hi8 ? x23 : x01;
            float y = hi8 ? x01 : x23;
            x += __shfl_xor_sync(0xffffffffu, y, 8);
            x += __shfl_xor_sync(0xffffffffu, x, 4);
            x += __shfl_xor_sync(0xffffffffu, x, 2);
            x += __shfl_xor_sync(0xffffffffu, x, 1);

            float e = (my_off == pad_off) ? 0.f : __expf(x);

            float att0 = __shfl_sync(0xffffffffu, e, 0);
            float att2 = __shfl_sync(0xffffffffu, e, 8);
            float att1 = __shfl_sync(0xffffffffu, e, 16);
            float att3 = __shfl_sync(0xffffffffu, e, 24);
            lsum += (att0 + att1) + (att2 + att3);

            a01.x = fmaf(att0, u0.x, fmaf(att1, u1.x, a01.x));
            a01.y = fmaf(att0, u0.y, fmaf(att1, u1.y, a01.y));
            a01.z = fmaf(att0, u0.z, fmaf(att1, u1.z, a01.z));
            a01.w = fmaf(att0, u0.w, fmaf(att1, u1.w, a01.w));
            a23.x = fmaf(att2, u2.x, fmaf(att3, u3.x, a23.x));
            a23.y = fmaf(att2, u2.y, fmaf(att3, u3.y, a23.y));
            a23.z = fmaf(att2, u2.z, fmaf(att3, u3.z, a23.z));
            a23.w = fmaf(att2, u2.w, fmaf(att3, u3.w, a23.w));
        };

        // rows 0..191: warp w4 handles m = w4*4 + it*16
        #pragma unroll 4
        for (int it = 0; it < 12; it++)
            body4(w4 * 4 + it * 16);
        // rows 192..199: warps w4==0,1 take one more 4-row group
        if (w4 < 2)
            body4(192 + w4 * 4);

        float4 at = make_float4(a01.x + a23.x, a01.y + a23.y,
                                a01.z + a23.z, a01.w + a23.w);
        reinterpret_cast<float4*>(s_aggp[wid])[lane] = at;
        if (lane == 0) s_red[wid] = lsum;
    }
    __syncthreads();

    // ---- Stage 3: reduce warp partials per side, normalize ----
    {
        int s = tid >> 7;
        int d = tid & 127;
        float tot = s_red[s * 4] + s_red[s * 4 + 1] + s_red[s * 4 + 2] + s_red[s * 4 + 3];
        float inv_sum = 1.f / tot;
        float a = s_aggp[s * 4][d] + s_aggp[s * 4 + 1][d]
                + s_aggp[s * 4 + 2][d] + s_aggp[s * 4 + 3][d];
        s_agg[s][d] = a * inv_sum;
    }
    __syncthreads();

    // ---- Stage 4: both matvecs share interleaved W loads (LDG.64) ----
    {
        int half = tid >> 7;
        int d    = tid & 127;
        int e0   = half * 64;
        float accL = 0.f, accR = 0.f;
        #pragma unroll 4
        for (int e = e0; e < e0 + 64; e++) {
            float2 w = g_Wp[e * EMBED + d];        // (wt, wh)
            accL = fmaf(s_agg[0][e],  w.x, accL);
            accL = fmaf(s_head[0][e], w.y, accL);
            accR = fmaf(s_agg[1][e],  w.x, accR);
            accR = fmaf(s_head[1][e], w.y, accR);
        }
        s_part[half][0][d] = accL;
        s_part[half][1][d] = accR;
    }
    __syncthreads();

    // ---- Stage 5: residual + LayerNorm per side ----
    {
        int s = tid >> 7;
        int d = tid & 127;
        float h = fmaxf(s_part[0][s][d] + s_part[1][s][d], 0.f);
        float x = h + s_head[s][d];

        float sx = x, sxx = x * x;
        #pragma unroll
        for (int o = 16; o; o >>= 1) {
            sx  += __shfl_xor_sync(0xffffffffu, sx,  o);
            sxx += __shfl_xor_sync(0xffffffffu, sxx, o);
        }
        if (lane == 0) { s_red[wid] = sx; s_red2[wid] = sxx; }
        __syncthreads();
        float tsum = s_red[s * 4]  + s_red[s * 4 + 1]  + s_red[s * 4 + 2]  + s_red[s * 4 + 3];
        float tsq  = s_red2[s * 4] + s_red2[s * 4 + 1] + s_red2[s * 4 + 2] + s_red2[s * 4 + 3];
        float mu      = tsum * (1.f / EMBED);
        float var     = tsq  * (1.f / EMBED) - mu * mu;
        float inv_std = rsqrtf(var + LN_EPS);
        float o = (x - mu) * inv_std * gamma[d] + beta[d];
        out[((long)s * batch + b) * EMBED + d] = o;
    }
}

extern "C" void kernel_launch(void* const* d_in, const int* in_sizes, int n_in,
                              void* d_out, int out_size) {
    const int*   entity = (const int*)  d_in[0];
    const int*   cl     = (const int*)  d_in[1];
    const int*   cr     = (const int*)  d_in[2];
    const float* emb    = (const float*)d_in[3];
    const float* W_bil  = (const float*)d_in[4];
    const float* W_tail = (const float*)d_in[5];
    const float* W_head = (const float*)d_in[6];
    const float* gamma  = (const float*)d_in[7];
    const float* beta   = (const float*)d_in[8];
    float* out = (float*)d_out;

    int batch   = in_sizes[0] / 2;             // 1024
    int pad_idx = in_sizes[3] / EMBED - 1;     // 100000

    transpose_w<<<(EMBED * EMBED + 255) / 256, 256>>>(W_tail, W_head);

    dim3 grid(batch);
    encoder_kernel<<<grid, NTHREADS>>>(entity, cl, cr, emb, W_bil,
                                       gamma, beta, out, batch, pad_idx);
}

// round 14
// speedup vs baseline: 1.0441x; 1.0441x over previous
#include <cuda_runtime.h>

#define EMBED     128
#define MAXN      200
#define NTHREADS  256
#define LN_EPS    1e-5f

// Interleaved pre-transposed weights: g_Wp[e*128+d] = (W_tail[d][e], W_head[d][e])
__device__ float2 g_Wp[EMBED * EMBED];

__global__ void transpose_w(const float* __restrict__ Wt, const float* __restrict__ Wh) {
    int i = blockIdx.x * blockDim.x + threadIdx.x;
    if (i < EMBED * EMBED) {
        int d = i >> 7;
        int e = i & 127;
        g_Wp[e * EMBED + d] = make_float2(Wt[i], Wh[i]);
    }
}

// One CTA = one batch element, BOTH sides. Score+exp+aggregate fused, 4 rows/iter.
// Gathers use __ldcs (streaming) so the 192KB weight working set stays L1-resident.
__global__ __launch_bounds__(NTHREADS, 4)
void encoder_kernel(const int*   __restrict__ entity,
                    const int*   __restrict__ conn_left,
                    const int*   __restrict__ conn_right,
                    const float* __restrict__ emb,
                    const float* __restrict__ W_bil,
                    const float* __restrict__ gamma,
                    const float* __restrict__ beta,
                    float*       __restrict__ out,
                    int batch, int pad_idx)
{
    const int b    = blockIdx.x;
    const int tid  = threadIdx.x;
    const int lane = tid & 31;
    const int wid  = tid >> 5;

    __shared__ float s_weak[EMBED];
    __shared__ float s_head[2][EMBED];
    __shared__ float s_qp[2 * EMBED];
    __shared__ __align__(16) unsigned s_roff[2][MAXN];   // rel row byte-offsets
    __shared__ __align__(16) unsigned s_toff[2][MAXN];   // tail row byte-offsets
    __shared__ float s_aggp[8][EMBED];
    __shared__ float s_agg[2][EMBED];
    __shared__ float s_part[2][2][EMBED];
    __shared__ float s_red[8];
    __shared__ float s_red2[8];

    // ---- Stage 0: heads, weak_rel, neighbor offsets for both sides ----
    if (tid < EMBED) {
        int e0 = entity[2 * b];
        int e1 = entity[2 * b + 1];
        float hl = __ldcs(&emb[(size_t)e0 * EMBED + tid]);
        float hr = __ldcs(&emb[(size_t)e1 * EMBED + tid]);
        s_weak[tid]    = hr - hl;
        s_head[0][tid] = hl;
        s_head[1][tid] = hr;
    }
    for (int i = tid; i < 2 * MAXN; i += NTHREADS) {
        int s = (i < MAXN) ? 0 : 1;
        int m = (i < MAXN) ? i : i - MAXN;
        const int* conn = (s == 0 ? conn_left : conn_right) + (long)b * MAXN * 2;
        int2 c = reinterpret_cast<const int2*>(conn)[m];
        s_roff[s][m] = (unsigned)c.x << 9;     // row * 512 bytes
        s_toff[s][m] = (unsigned)c.y << 9;
    }
    __syncthreads();

    // ---- Stage 1: q = weak_rel @ W_bil (shared by both sides), split-K ----
    {
        int half = tid >> 7;
        int e    = tid & 127;
        int d0   = half * 64;
        float acc = 0.f;
        #pragma unroll 8
        for (int d = d0; d < d0 + 64; d++)
            acc = fmaf(s_weak[d], W_bil[d * EMBED + e], acc);
        s_qp[half * EMBED + e] = acc;
    }
    __syncthreads();

    // ---- Stage 2 (FUSED): score -> exp -> aggregate, 4 rows per iteration ----
    {
        float4 q0 = reinterpret_cast<const float4*>(s_qp)[lane];
        float4 q1 = reinterpret_cast<const float4*>(s_qp + EMBED)[lane];
        float4 qv = make_float4(q0.x + q1.x, q0.y + q1.y, q0.z + q1.z, q0.w + q1.w);

        const char* embB = reinterpret_cast<const char*>(emb) + (unsigned)(lane << 4);
        const unsigned pad_off = (unsigned)pad_idx << 9;

        const int s    = wid >> 2;
        const int w4   = wid & 3;
        const bool hi16 = (lane & 16) != 0;
        const bool hi8  = (lane & 8)  != 0;

        float  lsum = 0.f;
        float4 a01 = make_float4(0.f, 0.f, 0.f, 0.f);
        float4 a23 = make_float4(0.f, 0.f, 0.f, 0.f);

        // 4-row fused body; m is a multiple of 4 (int4-aligned offset loads)
        auto body4 = [&](int m) {
            int4 ro = *reinterpret_cast<const int4*>(&s_roff[s][m]);
            int4 to = *reinterpret_cast<const int4*>(&s_toff[s][m]);
            // lane groups after reduce: [0-7]=row0, [8-15]=row2, [16-23]=row1, [24-31]=row3
            unsigned gA = hi8  ? (unsigned)ro.z : (unsigned)ro.x;
            unsigned gB = hi8  ? (unsigned)ro.w : (unsigned)ro.y;
            unsigned my_off = hi16 ? gB : gA;

            float4 v0 = __ldcs(reinterpret_cast<const float4*>(embB + (unsigned)ro.x));
            float4 v1 = __ldcs(reinterpret_cast<const float4*>(embB + (unsigned)ro.y));
            float4 v2 = __ldcs(reinterpret_cast<const float4*>(embB + (unsigned)ro.z));
            float4 v3 = __ldcs(reinterpret_cast<const float4*>(embB + (unsigned)ro.w));
            float4 u0 = __ldcs(reinterpret_cast<const float4*>(embB + (unsigned)to.x));
            float4 u1 = __ldcs(reinterpret_cast<const float4*>(embB + (unsigned)to.y));
            float4 u2 = __ldcs(reinterpret_cast<const float4*>(embB + (unsigned)to.z));
            float4 u3 = __ldcs(reinterpret_cast<const float4*>(embB + (unsigned)to.w));

            float p0 = v0.x*qv.x + v0.y*qv.y + v0.z*qv.z + v0.w*qv.w;
            float p1 = v1.x*qv.x + v1.y*qv.y + v1.z*qv.z + v1.w*qv.w;
            float p2 = v2.x*qv.x + v2.y*qv.y + v2.z*qv.z + v2.w*qv.w;
            float p3 = v3.x*qv.x + v3.y*qv.y + v3.z*qv.z + v3.w*qv.w;

            // 4-row reduce in 5 shfls
            float x01 = hi16 ? p1 : p0;
            float y01 = hi16 ? p0 : p1;
            x01 += __shfl_xor_sync(0xffffffffu, y01, 16);
            float x23 = hi16 ? p3 : p2;
            float y23 = hi16 ? p2 : p3;
            x23 += __shfl_xor_sync(0xffffffffu, y23, 16);
            float x = hi8 ? x23 : x01;
            float y = hi8 ? x01 : x23;
            x += __shfl_xor_sync(0xffffffffu, y, 8);
            x += __shfl_xor_sync(0xffffffffu, x, 4);
            x += __shfl_xor_sync(0xffffffffu, x, 2);
            x += __shfl_xor_sync(0xffffffffu, x, 1);

            float e = (my_off == pad_off) ? 0.f : __expf(x);

            float att0 = __shfl_sync(0xffffffffu, e, 0);
            float att2 = __shfl_sync(0xffffffffu, e, 8);
            float att1 = __shfl_sync(0xffffffffu, e, 16);
            float att3 = __shfl_sync(0xffffffffu, e, 24);
            lsum += (att0 + att1) + (att2 + att3);

            a01.x = fmaf(att0, u0.x, fmaf(att1, u1.x, a01.x));
            a01.y = fmaf(att0, u0.y, fmaf(att1, u1.y, a01.y));
            a01.z = fmaf(att0, u0.z, fmaf(att1, u1.z, a01.z));
            a01.w = fmaf(att0, u0.w, fmaf(att1, u1.w, a01.w));
            a23.x = fmaf(att2, u2.x, fmaf(att3, u3.x, a23.x));
            a23.y = fmaf(att2, u2.y, fmaf(att3, u3.y, a23.y));
            a23.z = fmaf(att2, u2.z, fmaf(att3, u3.z, a23.z));
            a23.w = fmaf(att2, u2.w, fmaf(att3, u3.w, a23.w));
        };

        // rows 0..191: warp w4 handles m = w4*4 + it*16
        #pragma unroll 4
        for (int it = 0; it < 12; it++)
            body4(w4 * 4 + it * 16);
        // rows 192..199: warps w4==0,1 take one more 4-row group
        if (w4 < 2)
            body4(192 + w4 * 4);

        float4 at = make_float4(a01.x + a23.x, a01.y + a23.y,
                                a01.z + a23.z, a01.w + a23.w);
        reinterpret_cast<float4*>(s_aggp[wid])[lane] = at;
        if (lane == 0) s_red[wid] = lsum;
    }
    __syncthreads();

    // ---- Stage 3: reduce warp partials per side, normalize ----
    {
        int s = tid >> 7;
        int d = tid & 127;
        float tot = s_red[s * 4] + s_red[s * 4 + 1] + s_red[s * 4 + 2] + s_red[s * 4 + 3];
        float inv_sum = 1.f / tot;
        float a = s_aggp[s * 4][d] + s_aggp[s * 4 + 1][d]
                + s_aggp[s * 4 + 2][d] + s_aggp[s * 4 + 3][d];
        s_agg[s][d] = a * inv_sum;
    }
    __syncthreads();

    // ---- Stage 4: both matvecs share interleaved W loads (LDG.64, L1-cached) ----
    {
        int half = tid >> 7;
        int d    = tid & 127;
        int e0   = half * 64;
        float accL = 0.f, accR = 0.f;
        #pragma unroll 4
        for (int e = e0; e < e0 + 64; e++) {
            float2 w = g_Wp[e * EMBED + d];        // (wt, wh)
            accL = fmaf(s_agg[0][e],  w.x, accL);
            accL = fmaf(s_head[0][e], w.y, accL);
            accR = fmaf(s_agg[1][e],  w.x, accR);
            accR = fmaf(s_head[1][e], w.y, accR);
        }
        s_part[half][0][d] = accL;
        s_part[half][1][d] = accR;
    }
    __syncthreads();

    // ---- Stage 5: residual + LayerNorm per side ----
    {
        int s = tid >> 7;
        int d = tid & 127;
        float h = fmaxf(s_part[0][s][d] + s_part[1][s][d], 0.f);
        float x = h + s_head[s][d];

        float sx = x, sxx = x * x;
        #pragma unroll
        for (int o = 16; o; o >>= 1) {
            sx  += __shfl_xor_sync(0xffffffffu, sx,  o);
            sxx += __shfl_xor_sync(0xffffffffu, sxx, o);
        }
        if (lane == 0) { s_red[wid] = sx; s_red2[wid] = sxx; }
        __syncthreads();
        float tsum = s_red[s * 4]  + s_red[s * 4 + 1]  + s_red[s * 4 + 2]  + s_red[s * 4 + 3];
        float tsq  = s_red2[s * 4] + s_red2[s * 4 + 1] + s_red2[s * 4 + 2] + s_red2[s * 4 + 3];
        float mu      = tsum * (1.f / EMBED);
        float var     = tsq  * (1.f / EMBED) - mu * mu;
        float inv_std = rsqrtf(var + LN_EPS);
        float o = (x - mu) * inv_std * gamma[d] + beta[d];
        out[((long)s * batch + b) * EMBED + d] = o;
    }
}

extern "C" void kernel_launch(void* const* d_in, const int* in_sizes, int n_in,
                              void* d_out, int out_size) {
    const int*   entity = (const int*)  d_in[0];
    const int*   cl     = (const int*)  d_in[1];
    const int*   cr     = (const int*)  d_in[2];
    const float* emb    = (const float*)d_in[3];
    const float* W_bil  = (const float*)d_in[4];
    const float* W_tail = (const float*)d_in[5];
    const float* W_head = (const float*)d_in[6];
    const float* gamma  = (const float*)d_in[7];
    const float* beta   = (const float*)d_in[8];
    float* out = (float*)d_out;

    int batch   = in_sizes[0] / 2;             // 1024
    int pad_idx = in_sizes[3] / EMBED - 1;     // 100000

    transpose_w<<<(EMBED * EMBED + 255) / 256, 256>>>(W_tail, W_head);

    dim3 grid(batch);
    encoder_kernel<<<grid, NTHREADS>>>(entity, cl, cr, emb, W_bil,
                                       gamma, beta, out, batch, pad_idx);
}